// round 1
// baseline (speedup 1.0000x reference)
#include <cuda_runtime.h>
#include <math.h>

#define HID 128
#define SDF_THRESH 5e-05f

// ---------------------------------------------------------------------------
// Stable softplus matching jax.nn.softplus: max(x,0) + log1p(exp(-|x|))
// ---------------------------------------------------------------------------
__device__ __forceinline__ float softplusf(float x) {
    return fmaxf(x, 0.0f) + log1pf(__expf(-fabsf(x)));
}

// ---------------------------------------------------------------------------
// One SDF eval: 3 -> 128 -> 128 -> 1 MLP, weights in shared memory.
// h1 kept fully in registers (inner loops fully unrolled).
// W2 is read row-major: for a group of 4 output units j..j+3, row k gives a
// contiguous float4 (broadcast LDS.128, conflict-free).
// ---------------------------------------------------------------------------
__device__ __forceinline__ float sdf_eval(
    float px, float py, float pz,
    const float*  __restrict__ sW1,   // [3][128]
    const float*  __restrict__ sb1,   // [128]
    const float4* __restrict__ sW2,   // [128][32] float4 view of [128][128]
    const float*  __restrict__ sb2,   // [128]
    const float*  __restrict__ sW3,   // [128]
    float b3)
{
    float h1[HID];
#pragma unroll
    for (int k = 0; k < HID; k += 4) {
        float4 w0 = *reinterpret_cast<const float4*>(sW1 + 0 * HID + k);
        float4 w1 = *reinterpret_cast<const float4*>(sW1 + 1 * HID + k);
        float4 w2 = *reinterpret_cast<const float4*>(sW1 + 2 * HID + k);
        float4 bb = *reinterpret_cast<const float4*>(sb1 + k);
        h1[k + 0] = softplusf(fmaf(px, w0.x, fmaf(py, w1.x, fmaf(pz, w2.x, bb.x))));
        h1[k + 1] = softplusf(fmaf(px, w0.y, fmaf(py, w1.y, fmaf(pz, w2.y, bb.y))));
        h1[k + 2] = softplusf(fmaf(px, w0.z, fmaf(py, w1.z, fmaf(pz, w2.z, bb.z))));
        h1[k + 3] = softplusf(fmaf(px, w0.w, fmaf(py, w1.w, fmaf(pz, w2.w, bb.w))));
    }

    float out = b3;
#pragma unroll 1
    for (int j = 0; j < HID; j += 4) {
        float a0 = sb2[j + 0];
        float a1 = sb2[j + 1];
        float a2 = sb2[j + 2];
        float a3 = sb2[j + 3];
        const float4* col = sW2 + (j >> 2);
#pragma unroll
        for (int k = 0; k < HID; k++) {
            float4 w = col[k * (HID / 4)];
            float  h = h1[k];
            a0 = fmaf(h, w.x, a0);
            a1 = fmaf(h, w.y, a1);
            a2 = fmaf(h, w.z, a2);
            a3 = fmaf(h, w.w, a3);
        }
        out = fmaf(softplusf(a0), sW3[j + 0], out);
        out = fmaf(softplusf(a1), sW3[j + 1], out);
        out = fmaf(softplusf(a2), sW3[j + 2], out);
        out = fmaf(softplusf(a3), sW3[j + 3], out);
    }
    return out;
}

// ---------------------------------------------------------------------------
// Persistent per-(channel,ray) sphere-trace. Thread t: ray = t>>1, ch = t&1,
// so the two channels of a ray sit in adjacent lanes (shfl_xor 1 exchange for
// the z0 < z1 cross-channel mask). Warp-level __any_sync skips SDF evals for
// warps where every lane is masked off (after iteration 1 this is ~all work).
// ---------------------------------------------------------------------------
__global__ void __launch_bounds__(128)
sphere_trace_kernel(const float* __restrict__ rays_d,
                    const float* __restrict__ rays_o,
                    const float* __restrict__ gW1,
                    const float* __restrict__ gb1,
                    const float* __restrict__ gW2,
                    const float* __restrict__ gb2,
                    const float* __restrict__ gW3,
                    const float* __restrict__ gb3,
                    float* __restrict__ out,
                    int n)
{
    extern __shared__ float smem[];
    float4* sW2 = reinterpret_cast<float4*>(smem);   // 16384 floats, 16B aligned
    float*  sW1 = smem + HID * HID;                   // 384
    float*  sb1 = sW1 + 3 * HID;                      // 128
    float*  sb2 = sb1 + HID;                          // 128
    float*  sW3 = sb2 + HID;                          // 128

    for (int i = threadIdx.x; i < HID * HID; i += blockDim.x) smem[i] = gW2[i];
    for (int i = threadIdx.x; i < 3 * HID; i += blockDim.x)   sW1[i] = gW1[i];
    for (int i = threadIdx.x; i < HID; i += blockDim.x) {
        sb1[i] = gb1[i];
        sb2[i] = gb2[i];
        sW3[i] = gW3[i];
    }
    float b3 = gb3[0];
    __syncthreads();

    const int total = 2 * n;
    int t = blockIdx.x * blockDim.x + threadIdx.x;
    const bool valid = (t < total);
    int tc  = valid ? t : (total - 1);
    int ray = tc >> 1;
    int ch  = tc & 1;
    float sgn = ch ? -1.0f : 1.0f;

    float dx = rays_d[ray * 3 + 0];
    float dy = rays_d[ray * 3 + 1];
    float dz = rays_d[ray * 3 + 2];
    float ox = rays_o[ray * 3 + 0];
    float oy = rays_o[ray * 3 + 1];
    float oz = rays_o[ray * 3 + 2];

    float z = 0.0f;
    float next_sdf = sdf_eval(ox, oy, oz, sW1, sb1, sW2, sb2, sW3, b3);
    bool  mask = true;

#pragma unroll 1
    for (int it = 0; it < 6; it++) {
        float sdf_vals = mask ? next_sdf : 0.0f;
        if (sdf_vals <= SDF_THRESH) sdf_vals = 0.0f;
        mask = mask && (sdf_vals > SDF_THRESH);
        z = fmaf(sgn, sdf_vals, z);

        bool need = mask;
        if (__any_sync(0xFFFFFFFFu, need)) {
            float s = sdf_eval(fmaf(z, dx, ox), fmaf(z, dy, oy), fmaf(z, dz, oz),
                               sW1, sb1, sW2, sb2, sW3, b3);
            next_sdf = need ? s : 0.0f;
        } else {
            next_sdf = 0.0f;
        }

        bool fmask = next_sdf < 0.0f;
#pragma unroll 1
        for (int i = 0; i < 3; i++) {
            float step = 0.5f / (float)(1 << i);   // 0.5, 0.25, 0.125 exact
            if (__any_sync(0xFFFFFFFFu, fmask)) {
                float zc = fmask ? (z - step * sgn * sdf_vals) : z;
                float s2 = sdf_eval(fmaf(zc, dx, ox), fmaf(zc, dy, oy), fmaf(zc, dz, oz),
                                    sW1, sb1, sW2, sb2, sW3, b3);
                z = zc;
                if (fmask) next_sdf = s2;
            }
            fmask = next_sdf < 0.0f;
        }

        // mask &= (z_ch0 < z_ch1), broadcast to both channels of the ray
        float zo = __shfl_xor_sync(0xFFFFFFFFu, z, 1);
        bool cond = (ch == 0) ? (z < zo) : (zo < z);
        mask = mask && cond;
    }

    // final top-of-loop mask update
    {
        float sdf_vals = mask ? next_sdf : 0.0f;
        if (sdf_vals <= SDF_THRESH) sdf_vals = 0.0f;
        mask = mask && (sdf_vals > SDF_THRESH);
    }

    if (valid) {
        // invariant: points == z*d + o at every point the reference updates it
        float px = fmaf(z, dx, ox);
        float py = fmaf(z, dy, oy);
        float pz = fmaf(z, dz, oz);
        long base = (long)ch * n + ray;
        // output layout: points (2,n,3) | z_vals (2,n) | mask (2,n)
        out[base * 3 + 0] = px;
        out[base * 3 + 1] = py;
        out[base * 3 + 2] = pz;
        out[(long)6 * n + base] = z;
        out[(long)8 * n + base] = mask ? 1.0f : 0.0f;
    }
}

extern "C" void kernel_launch(void* const* d_in, const int* in_sizes, int n_in,
                              void* d_out, int out_size)
{
    const float* rays_d = (const float*)d_in[0];
    const float* rays_o = (const float*)d_in[1];
    const float* W1     = (const float*)d_in[2];
    const float* b1     = (const float*)d_in[3];
    const float* W2     = (const float*)d_in[4];
    const float* b2     = (const float*)d_in[5];
    const float* W3     = (const float*)d_in[6];
    const float* b3     = (const float*)d_in[7];

    int n = in_sizes[0] / 3;        // N_RAYS
    int total = 2 * n;
    int block = 128;
    int grid = (total + block - 1) / block;

    size_t smem_bytes = (size_t)(HID * HID + 3 * HID + 3 * HID) * sizeof(float); // 68608

    cudaFuncSetAttribute(sphere_trace_kernel,
                         cudaFuncAttributeMaxDynamicSharedMemorySize,
                         (int)smem_bytes);

    sphere_trace_kernel<<<grid, block, smem_bytes>>>(
        rays_d, rays_o, W1, b1, W2, b2, W3, b3, (float*)d_out, n);
}

// round 2
// speedup vs baseline: 1.1976x; 1.1976x over previous
#include <cuda_runtime.h>
#include <cstdint>
#include <math.h>

#define HID 128
#define SDF_THRESH 5e-05f

// ---------------------------------------------------------------------------
// f32x2 packed-math helpers (Blackwell sm_100: FFMA2 via PTX fma.rn.f32x2)
// ---------------------------------------------------------------------------
__device__ __forceinline__ unsigned long long pack2(float lo, float hi) {
    unsigned long long r;
    asm("mov.b64 %0, {%1,%2};" : "=l"(r) : "f"(lo), "f"(hi));
    return r;
}
__device__ __forceinline__ void unpack2(unsigned long long v, float& lo, float& hi) {
    asm("mov.b64 {%0,%1}, %2;" : "=f"(lo), "=f"(hi) : "l"(v));
}
__device__ __forceinline__ unsigned long long fma2(unsigned long long a,
                                                   unsigned long long b,
                                                   unsigned long long c) {
    unsigned long long d;
    asm("fma.rn.f32x2 %0, %1, %2, %3;" : "=l"(d) : "l"(a), "l"(b), "l"(c));
    return d;
}
// 16B shared load as two b64 (one LDS.128, broadcast when all lanes agree)
__device__ __forceinline__ void lds_v2u64(uint32_t addr,
                                          unsigned long long& a,
                                          unsigned long long& b) {
    asm volatile("ld.shared.v2.u64 {%0,%1}, [%2];" : "=l"(a), "=l"(b) : "r"(addr));
}

// Stable softplus matching jax.nn.softplus (same as R1, which passed 1.3e-6)
__device__ __forceinline__ float softplusf(float x) {
    return fmaxf(x, 0.0f) + log1pf(__expf(-fabsf(x)));
}

// ---------------------------------------------------------------------------
// Shared layout (float offsets):
//   [0, 16384)          W2 packed: entry (kp, j) at 2*(kp*128 + j) holds
//                       { W2[2kp][j], W2[2kp+1][j] }   (64KB)
//   [16384, 16768)      W1  [3][128]
//   [16768, 16896)      b1
//   [16896, 17024)      b2
//   [17024, 17152)      W3
// ---------------------------------------------------------------------------
#define OFF_W2   0
#define OFF_W1   16384
#define OFF_B1   16768
#define OFF_B2   16896
#define OFF_W3   17024
#define SMEM_FLOATS 17152

// ---------------------------------------------------------------------------
// One SDF eval: 3 -> 128 -> 128 -> 1 MLP, all f32x2 packed.
// hp[64] = packed (h_2k, h_2k+1) pairs held in registers.
// noinline: one ~20KB body instead of 5 inlined copies (I$).
// ---------------------------------------------------------------------------
__device__ __noinline__ float sdf_eval(float px, float py, float pz,
                                       uint32_t sb,     // shared base addr (bytes)
                                       const float* __restrict__ smem,
                                       float b3)
{
    const uint32_t aW2 = sb + OFF_W2 * 4u;
    const uint32_t aW1 = sb + OFF_W1 * 4u;
    const uint32_t aB1 = sb + OFF_B1 * 4u;

    unsigned long long hp[HID / 2];

    // ---- layer 1: 3 -> 128 ----
    unsigned long long pxx = pack2(px, px);
    unsigned long long pyy = pack2(py, py);
    unsigned long long pzz = pack2(pz, pz);
#pragma unroll
    for (int k = 0; k < HID; k += 4) {
        unsigned long long w0a, w0b, w1a, w1b, w2a, w2b, ba, bb;
        lds_v2u64(aW1 + k * 4u,                  w0a, w0b);   // W1 row 0
        lds_v2u64(aW1 + 512u + k * 4u,           w1a, w1b);   // W1 row 1
        lds_v2u64(aW1 + 1024u + k * 4u,          w2a, w2b);   // W1 row 2
        lds_v2u64(aB1 + k * 4u,                  ba,  bb);
        unsigned long long t0 = fma2(pxx, w0a, fma2(pyy, w1a, fma2(pzz, w2a, ba)));
        unsigned long long t1 = fma2(pxx, w0b, fma2(pyy, w1b, fma2(pzz, w2b, bb)));
        float x0, x1, x2, x3;
        unpack2(t0, x0, x1);
        unpack2(t1, x2, x3);
        hp[(k >> 1) + 0] = pack2(softplusf(x0), softplusf(x1));
        hp[(k >> 1) + 1] = pack2(softplusf(x2), softplusf(x3));
    }

    // ---- layer 2 + layer 3: 128 -> 128 -> 1 ----
    const float* sb2 = smem + OFF_B2;
    const float* sW3 = smem + OFF_W3;
    float out = b3;
#pragma unroll 1
    for (int j = 0; j < HID; j += 4) {
        // acc_j = (sum over even k, sum over odd k), bias in even slot
        unsigned long long a0 = pack2(sb2[j + 0], 0.0f);
        unsigned long long a1 = pack2(sb2[j + 1], 0.0f);
        unsigned long long a2 = pack2(sb2[j + 2], 0.0f);
        unsigned long long a3 = pack2(sb2[j + 3], 0.0f);
        const uint32_t base = aW2 + (uint32_t)j * 8u;
#pragma unroll
        for (int kp = 0; kp < HID / 2; kp++) {
            unsigned long long w0, w1, w2, w3;
            lds_v2u64(base + (uint32_t)kp * 1024u,       w0, w1);
            lds_v2u64(base + (uint32_t)kp * 1024u + 16u, w2, w3);
            unsigned long long h = hp[kp];
            a0 = fma2(h, w0, a0);
            a1 = fma2(h, w1, a1);
            a2 = fma2(h, w2, a2);
            a3 = fma2(h, w3, a3);
        }
        float e, o;
        unpack2(a0, e, o); out = fmaf(softplusf(e + o), sW3[j + 0], out);
        unpack2(a1, e, o); out = fmaf(softplusf(e + o), sW3[j + 1], out);
        unpack2(a2, e, o); out = fmaf(softplusf(e + o), sW3[j + 2], out);
        unpack2(a3, e, o); out = fmaf(softplusf(e + o), sW3[j + 3], out);
    }
    return out;
}

// ---------------------------------------------------------------------------
// Persistent per-(channel,ray) sphere trace. Thread t: ray = t>>1, ch = t&1;
// the two channels of a ray are adjacent lanes (shfl_xor 1 for z0<z1 mask).
// Warp-level __any_sync skips whole SDF evals for fully-masked warps.
// ---------------------------------------------------------------------------
__global__ void __launch_bounds__(128)
sphere_trace_kernel(const float* __restrict__ rays_d,
                    const float* __restrict__ rays_o,
                    const float* __restrict__ gW1,
                    const float* __restrict__ gb1,
                    const float* __restrict__ gW2,
                    const float* __restrict__ gb2,
                    const float* __restrict__ gW3,
                    const float* __restrict__ gb3,
                    float* __restrict__ out,
                    int n)
{
    extern __shared__ float smem[];

    // Pack W2 into (k, k+1) pairs: float offset 2*(kp*128+j) = {W2[2kp][j], W2[2kp+1][j]}
    for (int idx = threadIdx.x; idx < (HID / 2) * HID; idx += blockDim.x) {
        int kp = idx >> 7;
        int j  = idx & 127;
        smem[2 * idx + 0] = gW2[kp * 256 + j];
        smem[2 * idx + 1] = gW2[kp * 256 + 128 + j];
    }
    for (int i = threadIdx.x; i < 3 * HID; i += blockDim.x) smem[OFF_W1 + i] = gW1[i];
    for (int i = threadIdx.x; i < HID; i += blockDim.x) {
        smem[OFF_B1 + i] = gb1[i];
        smem[OFF_B2 + i] = gb2[i];
        smem[OFF_W3 + i] = gW3[i];
    }
    float b3 = gb3[0];
    __syncthreads();

    uint32_t sb = (uint32_t)__cvta_generic_to_shared(smem);

    const int total = 2 * n;
    int t = blockIdx.x * blockDim.x + threadIdx.x;
    const bool valid = (t < total);
    int tc  = valid ? t : (total - 1);
    int ray = tc >> 1;
    int ch  = tc & 1;
    float sgn = ch ? -1.0f : 1.0f;

    float dx = rays_d[ray * 3 + 0];
    float dy = rays_d[ray * 3 + 1];
    float dz = rays_d[ray * 3 + 2];
    float ox = rays_o[ray * 3 + 0];
    float oy = rays_o[ray * 3 + 1];
    float oz = rays_o[ray * 3 + 2];

    float z = 0.0f;
    float next_sdf = sdf_eval(ox, oy, oz, sb, smem, b3);
    bool  mask = true;

#pragma unroll 1
    for (int it = 0; it < 6; it++) {
        float sdf_vals = mask ? next_sdf : 0.0f;
        if (sdf_vals <= SDF_THRESH) sdf_vals = 0.0f;
        mask = mask && (sdf_vals > SDF_THRESH);
        z = fmaf(sgn, sdf_vals, z);

        if (__any_sync(0xFFFFFFFFu, mask)) {
            float s = sdf_eval(fmaf(z, dx, ox), fmaf(z, dy, oy), fmaf(z, dz, oz),
                               sb, smem, b3);
            next_sdf = mask ? s : 0.0f;
        } else {
            next_sdf = 0.0f;
        }

        bool fmask = next_sdf < 0.0f;
#pragma unroll 1
        for (int i = 0; i < 3; i++) {
            float step = 0.5f / (float)(1 << i);   // 0.5, 0.25, 0.125 exact
            if (__any_sync(0xFFFFFFFFu, fmask)) {
                float zc = fmask ? (z - step * sgn * sdf_vals) : z;
                float s2 = sdf_eval(fmaf(zc, dx, ox), fmaf(zc, dy, oy), fmaf(zc, dz, oz),
                                    sb, smem, b3);
                z = zc;
                if (fmask) next_sdf = s2;
            }
            fmask = next_sdf < 0.0f;
        }

        // mask &= (z_ch0 < z_ch1), broadcast to both channels of the ray
        float zo = __shfl_xor_sync(0xFFFFFFFFu, z, 1);
        bool cond = (ch == 0) ? (z < zo) : (zo < z);
        mask = mask && cond;
    }

    // final top-of-loop mask update
    {
        float sdf_vals = mask ? next_sdf : 0.0f;
        if (sdf_vals <= SDF_THRESH) sdf_vals = 0.0f;
        mask = mask && (sdf_vals > SDF_THRESH);
    }

    if (valid) {
        float px = fmaf(z, dx, ox);
        float py = fmaf(z, dy, oy);
        float pz = fmaf(z, dz, oz);
        long base = (long)ch * n + ray;
        // output layout: points (2,n,3) | z_vals (2,n) | mask (2,n)
        out[base * 3 + 0] = px;
        out[base * 3 + 1] = py;
        out[base * 3 + 2] = pz;
        out[(long)6 * n + base] = z;
        out[(long)8 * n + base] = mask ? 1.0f : 0.0f;
    }
}

extern "C" void kernel_launch(void* const* d_in, const int* in_sizes, int n_in,
                              void* d_out, int out_size)
{
    const float* rays_d = (const float*)d_in[0];
    const float* rays_o = (const float*)d_in[1];
    const float* W1     = (const float*)d_in[2];
    const float* b1     = (const float*)d_in[3];
    const float* W2     = (const float*)d_in[4];
    const float* b2     = (const float*)d_in[5];
    const float* W3     = (const float*)d_in[6];
    const float* b3     = (const float*)d_in[7];

    int n = in_sizes[0] / 3;        // N_RAYS
    int total = 2 * n;
    int block = 128;
    int grid = (total + block - 1) / block;

    size_t smem_bytes = (size_t)SMEM_FLOATS * sizeof(float);   // 68608

    cudaFuncSetAttribute(sphere_trace_kernel,
                         cudaFuncAttributeMaxDynamicSharedMemorySize,
                         (int)smem_bytes);

    sphere_trace_kernel<<<grid, block, smem_bytes>>>(
        rays_d, rays_o, W1, b1, W2, b2, W3, b3, (float*)d_out, n);
}

// round 4
// speedup vs baseline: 2.2042x; 1.8405x over previous
#include <cuda_runtime.h>
#include <cuda_fp16.h>
#include <cstdint>
#include <math.h>

#define HID 128
#define SDF_THRESH 5e-05f
#define ROWB 272              // padded row stride (bytes) for fp16[128] rows

// shared-memory byte offsets (all 16B aligned)
#define SA_HI 0               // A hi: 256 rows x 272B = 69632
#define SA_LO 69632           // A lo: 69632
#define SW_HI 139264          // W2^T hi: 128 x 272 = 34816
#define SW_LO 174080          // W2^T lo: 34816
#define OFF_W1 208896         // fp32 [3][128] = 1536
#define OFF_B1 210432         // 512
#define OFF_B2 210944         // 512
#define OFF_W3 211456         // 512
#define OFF_RES 211968        // fp32 [256] = 1024
#define SMEM_TOTAL 212992

// Stable softplus matching jax.nn.softplus (proven in R1/R2)
__device__ __forceinline__ float softplusf(float x) {
    return fmaxf(x, 0.0f) + log1pf(__expf(-fabsf(x)));
}

__device__ __forceinline__ void ldsm4(uint32_t* r, uint32_t a) {
    asm volatile("ldmatrix.sync.aligned.m8n8.x4.shared.b16 {%0,%1,%2,%3}, [%4];"
        : "=r"(r[0]), "=r"(r[1]), "=r"(r[2]), "=r"(r[3]) : "r"(a));
}
__device__ __forceinline__ void mma16816(float* c, const uint32_t* a, const uint32_t* b) {
    asm volatile("mma.sync.aligned.m16n8k16.row.col.f32.f16.f16.f32 "
        "{%0,%1,%2,%3}, {%4,%5,%6,%7}, {%8,%9}, {%0,%1,%2,%3};"
        : "+f"(c[0]), "+f"(c[1]), "+f"(c[2]), "+f"(c[3])
        : "r"(a[0]), "r"(a[1]), "r"(a[2]), "r"(a[3]), "r"(b[0]), "r"(b[1]));
}

// ---------------------------------------------------------------------------
// Warp-collective SDF eval for this warp's 32 points (rows wbase..wbase+31).
// Layer 1 scalar -> h hi/lo fp16 rows in SMEM -> mma.sync GEMM vs W2 hi/lo
// (3 products, fp32 accumulate) -> softplus -> dot W3, quad-reduced.
// Per-warp independent: touches only its own A rows / result slots.
// ---------------------------------------------------------------------------
__device__ __noinline__ float sdf_eval_warp(float px, float py, float pz, float b3)
{
    extern __shared__ char dsm[];
    const int tid  = threadIdx.x;
    const int lane = tid & 31;
    const int wbase = tid & ~31;          // warp's first row
    const uint32_t smem0 = (uint32_t)__cvta_generic_to_shared(dsm);
    const float* sW1 = (const float*)(dsm + OFF_W1);
    const float* sb1 = (const float*)(dsm + OFF_B1);
    const float* sb2 = (const float*)(dsm + OFF_B2);
    const float* sW3 = (const float*)(dsm + OFF_W3);
    float* s_res = (float*)(dsm + OFF_RES);

    __syncwarp();   // prior eval's reads done before we overwrite A rows

    // ---- layer 1: 3 -> 128, store hi/lo fp16 into this thread's A row ----
    {
        char* arh = dsm + SA_HI + tid * ROWB;
        char* arl = dsm + SA_LO + tid * ROWB;
#pragma unroll
        for (int k = 0; k < HID; k += 8) {
            uint32_t hi[4], lo[4];
#pragma unroll
            for (int j = 0; j < 4; j++) {
                int k0 = k + 2 * j, k1 = k0 + 1;
                float pre0 = fmaf(px, sW1[k0], fmaf(py, sW1[128 + k0],
                             fmaf(pz, sW1[256 + k0], sb1[k0])));
                float pre1 = fmaf(px, sW1[k1], fmaf(py, sW1[128 + k1],
                             fmaf(pz, sW1[256 + k1], sb1[k1])));
                float h0 = fminf(softplusf(pre0), 60000.0f);
                float h1 = fminf(softplusf(pre1), 60000.0f);
                __half a0 = __float2half_rn(h0), a1 = __float2half_rn(h1);
                __half r0 = __float2half_rn(h0 - __half2float(a0));
                __half r1 = __float2half_rn(h1 - __half2float(a1));
                __half2 hh = __halves2half2(a0, a1);
                __half2 ll = __halves2half2(r0, r1);
                hi[j] = *(uint32_t*)&hh;
                lo[j] = *(uint32_t*)&ll;
            }
            *(uint4*)(arh + k * 2) = make_uint4(hi[0], hi[1], hi[2], hi[3]);
            *(uint4*)(arl + k * 2) = make_uint4(lo[0], lo[1], lo[2], lo[3]);
        }
    }
    __syncwarp();

    // ---- hoist all A fragments (hi + lo): 128 regs ----
    const uint32_t a_lane_off =
        (uint32_t)((wbase + ((lane >> 3) & 1) * 8 + (lane & 7)) * ROWB
                   + ((lane >> 4) * 16));
    uint32_t ah[2][8][4], al[2][8][4];
#pragma unroll
    for (int mt = 0; mt < 2; mt++)
#pragma unroll
        for (int kt = 0; kt < 8; kt++) {
            ldsm4(ah[mt][kt], smem0 + SA_HI + a_lane_off + mt * (16 * ROWB) + kt * 32);
            ldsm4(al[mt][kt], smem0 + SA_LO + a_lane_off + mt * (16 * ROWB) + kt * 32);
        }

    const uint32_t b_lane_off = (uint32_t)((lane & 7) * ROWB + (lane >> 3) * 16);
    const int tig = lane & 3;

    float p[4] = {0.f, 0.f, 0.f, 0.f};
#pragma unroll 1
    for (int npair = 0; npair < 8; npair++) {
        int na = npair * 16, nb = na + 8;
        float b2aa = sb2[na + 2 * tig], b2ab = sb2[na + 2 * tig + 1];
        float b2ba = sb2[nb + 2 * tig], b2bb = sb2[nb + 2 * tig + 1];
        // cm: Ah*Bh + Ah*Bl (seeded with b2); cx: Al*Bh
        float cm[2][2][4], cx[2][2][4];
#pragma unroll
        for (int mt = 0; mt < 2; mt++) {
            cm[0][mt][0] = b2aa; cm[0][mt][1] = b2ab; cm[0][mt][2] = b2aa; cm[0][mt][3] = b2ab;
            cm[1][mt][0] = b2ba; cm[1][mt][1] = b2bb; cm[1][mt][2] = b2ba; cm[1][mt][3] = b2bb;
#pragma unroll
            for (int i = 0; i < 4; i++) { cx[0][mt][i] = 0.f; cx[1][mt][i] = 0.f; }
        }
#pragma unroll
        for (int ktp = 0; ktp < 4; ktp++) {
            uint32_t bh[2][4], bl[2][4];
            ldsm4(bh[0], smem0 + SW_HI + (uint32_t)na * ROWB + ktp * 64 + b_lane_off);
            ldsm4(bl[0], smem0 + SW_LO + (uint32_t)na * ROWB + ktp * 64 + b_lane_off);
            ldsm4(bh[1], smem0 + SW_HI + (uint32_t)nb * ROWB + ktp * 64 + b_lane_off);
            ldsm4(bl[1], smem0 + SW_LO + (uint32_t)nb * ROWB + ktp * 64 + b_lane_off);
#pragma unroll
            for (int kk = 0; kk < 2; kk++) {
                int kt = 2 * ktp + kk;
#pragma unroll
                for (int ntx = 0; ntx < 2; ntx++)
#pragma unroll
                    for (int mt = 0; mt < 2; mt++) {
                        mma16816(cm[ntx][mt], ah[mt][kt], &bh[ntx][kk * 2]);
                        mma16816(cm[ntx][mt], ah[mt][kt], &bl[ntx][kk * 2]);
                        mma16816(cx[ntx][mt], al[mt][kt], &bh[ntx][kk * 2]);
                    }
            }
        }
        // epilogue for these 16 n-columns
        float w3aa = sW3[na + 2 * tig], w3ab = sW3[na + 2 * tig + 1];
        float w3ba = sW3[nb + 2 * tig], w3bb = sW3[nb + 2 * tig + 1];
#pragma unroll
        for (int ntx = 0; ntx < 2; ntx++) {
            float wa = ntx ? w3ba : w3aa;
            float wb = ntx ? w3bb : w3ab;
#pragma unroll
            for (int mt = 0; mt < 2; mt++) {
                float d0 = cm[ntx][mt][0] + cx[ntx][mt][0];
                float d1 = cm[ntx][mt][1] + cx[ntx][mt][1];
                float d2 = cm[ntx][mt][2] + cx[ntx][mt][2];
                float d3 = cm[ntx][mt][3] + cx[ntx][mt][3];
                p[mt * 2 + 0] = fmaf(softplusf(d0), wa, fmaf(softplusf(d1), wb, p[mt * 2 + 0]));
                p[mt * 2 + 1] = fmaf(softplusf(d2), wa, fmaf(softplusf(d3), wb, p[mt * 2 + 1]));
            }
        }
    }
    // quad reduction (cols split across tig) then route to owning thread
#pragma unroll
    for (int i = 0; i < 4; i++) {
        p[i] += __shfl_xor_sync(0xFFFFFFFFu, p[i], 1);
        p[i] += __shfl_xor_sync(0xFFFFFFFFu, p[i], 2);
    }
    if (tig == 0) {
        int g = lane >> 2;
        s_res[wbase + g +  0] = p[0];   // mt0 rows g
        s_res[wbase + g +  8] = p[1];   // mt0 rows g+8
        s_res[wbase + g + 16] = p[2];   // mt1 rows g+16
        s_res[wbase + g + 24] = p[3];   // mt1 rows g+24
    }
    __syncwarp();
    return b3 + s_res[tid];
}

// ---------------------------------------------------------------------------
__global__ void __launch_bounds__(256, 1)
sphere_trace_kernel(const float* __restrict__ rays_d,
                    const float* __restrict__ rays_o,
                    const float* __restrict__ gW1,
                    const float* __restrict__ gb1,
                    const float* __restrict__ gW2,
                    const float* __restrict__ gb2,
                    const float* __restrict__ gW3,
                    const float* __restrict__ gb3,
                    float* __restrict__ out,
                    int n)
{
    extern __shared__ char dsm[];
    const int tid = threadIdx.x;

    // stage W2^T hi/lo fp16 (coalesced gmem reads), n-major rows, k contiguous
    for (int idx = tid; idx < HID * HID; idx += blockDim.x) {
        int k = idx >> 7, nn = idx & 127;
        float w = gW2[idx];                       // gW2[k*128 + nn]
        __half h = __float2half_rn(w);
        __half l = __float2half_rn(w - __half2float(h));
        *(__half*)(dsm + SW_HI + nn * ROWB + k * 2) = h;
        *(__half*)(dsm + SW_LO + nn * ROWB + k * 2) = l;
    }
    {
        float* sW1 = (float*)(dsm + OFF_W1);
        float* sb1 = (float*)(dsm + OFF_B1);
        float* sb2 = (float*)(dsm + OFF_B2);
        float* sW3 = (float*)(dsm + OFF_W3);
        for (int i = tid; i < 3 * HID; i += blockDim.x) sW1[i] = gW1[i];
        for (int i = tid; i < HID; i += blockDim.x) {
            sb1[i] = gb1[i];
            sb2[i] = gb2[i];
            sW3[i] = gW3[i];
        }
    }
    float b3 = gb3[0];
    __syncthreads();

    const int total = 2 * n;
    int t = blockIdx.x * blockDim.x + tid;
    const bool valid = (t < total);
    int tc  = valid ? t : (total - 1);
    int ray = tc >> 1;
    int ch  = tc & 1;
    float sgn = ch ? -1.0f : 1.0f;

    float dx = rays_d[ray * 3 + 0];
    float dy = rays_d[ray * 3 + 1];
    float dz = rays_d[ray * 3 + 2];
    float ox = rays_o[ray * 3 + 0];
    float oy = rays_o[ray * 3 + 1];
    float oz = rays_o[ray * 3 + 2];

    float z = 0.0f;
    float next_sdf = sdf_eval_warp(ox, oy, oz, b3);
    bool mask = true;

#pragma unroll 1
    for (int it = 0; it < 6; it++) {
        float sdf_vals = mask ? next_sdf : 0.0f;
        if (sdf_vals <= SDF_THRESH) sdf_vals = 0.0f;
        mask = mask && (sdf_vals > SDF_THRESH);
        z = fmaf(sgn, sdf_vals, z);

        if (__any_sync(0xFFFFFFFFu, mask)) {
            float s = sdf_eval_warp(fmaf(z, dx, ox), fmaf(z, dy, oy),
                                    fmaf(z, dz, oz), b3);
            next_sdf = mask ? s : 0.0f;
        } else {
            next_sdf = 0.0f;
        }

        bool fmask = next_sdf < 0.0f;
#pragma unroll 1
        for (int i = 0; i < 3; i++) {
            float step = 0.5f / (float)(1 << i);   // 0.5, 0.25, 0.125 exact
            if (__any_sync(0xFFFFFFFFu, fmask)) {
                float zc = fmask ? (z - step * sgn * sdf_vals) : z;
                float s2 = sdf_eval_warp(fmaf(zc, dx, ox), fmaf(zc, dy, oy),
                                         fmaf(zc, dz, oz), b3);
                z = zc;
                if (fmask) next_sdf = s2;
            }
            fmask = next_sdf < 0.0f;
        }

        // mask &= (z_ch0 < z_ch1): channels are adjacent lanes
        float zo = __shfl_xor_sync(0xFFFFFFFFu, z, 1);
        bool cond = (ch == 0) ? (z < zo) : (zo < z);
        mask = mask && cond;
    }

    {   // final top-of-loop mask update
        float sdf_vals = mask ? next_sdf : 0.0f;
        if (sdf_vals <= SDF_THRESH) sdf_vals = 0.0f;
        mask = mask && (sdf_vals > SDF_THRESH);
    }

    if (valid) {
        float px = fmaf(z, dx, ox);
        float py = fmaf(z, dy, oy);
        float pz = fmaf(z, dz, oz);
        long basei = (long)ch * n + ray;
        // output layout: points (2,n,3) | z_vals (2,n) | mask (2,n)
        out[basei * 3 + 0] = px;
        out[basei * 3 + 1] = py;
        out[basei * 3 + 2] = pz;
        out[(long)6 * n + basei] = z;
        out[(long)8 * n + basei] = mask ? 1.0f : 0.0f;
    }
}

extern "C" void kernel_launch(void* const* d_in, const int* in_sizes, int n_in,
                              void* d_out, int out_size)
{
    const float* rays_d = (const float*)d_in[0];
    const float* rays_o = (const float*)d_in[1];
    const float* W1     = (const float*)d_in[2];
    const float* b1     = (const float*)d_in[3];
    const float* W2     = (const float*)d_in[4];
    const float* b2     = (const float*)d_in[5];
    const float* W3     = (const float*)d_in[6];
    const float* b3     = (const float*)d_in[7];

    int n = in_sizes[0] / 3;        // N_RAYS
    int total = 2 * n;
    int block = 256;
    int grid = (total + block - 1) / block;

    cudaFuncSetAttribute(sphere_trace_kernel,
                         cudaFuncAttributeMaxDynamicSharedMemorySize,
                         SMEM_TOTAL);

    sphere_trace_kernel<<<grid, block, SMEM_TOTAL>>>(
        rays_d, rays_o, W1, b1, W2, b2, W3, b3, (float*)d_out, n);
}

// round 5
// speedup vs baseline: 3.3330x; 1.5121x over previous
#include <cuda_runtime.h>
#include <cuda_fp16.h>
#include <cstdint>
#include <math.h>

#define HID 128
#define SDF_THRESH 5e-05f
#define ROWB 272              // padded row stride (bytes) for fp16[128] rows

// shared-memory byte offsets (per-CTA dynamic, all 16B aligned)
#define SW_HI  0              // W2' hi: 128 rows x 272B = 34816  (W2'[m][k] = W2[k][m])
#define SW_LO  34816          // W2' lo: 34816
#define OFF_W1 69632          // fp32 [3][128] = 1536
#define OFF_B1 71168          // 512
#define OFF_B2 71680          // 512
#define OFF_W3 72192          // 512
#define OFF_RES 72704         // fp32 [256] = 1024
#define SMEM_TOTAL 73728      // 72 KB -> 2 CTAs/SM

// softplus: max(x,0) + log(1 + exp(-|x|))  (2 MUFU; ~1e-7 abs vs log1pf)
__device__ __forceinline__ float softplusf(float x) {
    float u = __expf(-fabsf(x));
    return fmaxf(x, 0.0f) + __logf(1.0f + u);
}

__device__ __forceinline__ void ldsm4(uint32_t* r, uint32_t a) {
    asm volatile("ldmatrix.sync.aligned.m8n8.x4.shared.b16 {%0,%1,%2,%3}, [%4];"
        : "=r"(r[0]), "=r"(r[1]), "=r"(r[2]), "=r"(r[3]) : "r"(a));
}
__device__ __forceinline__ void mma16816(float* c, const uint32_t* a, const uint32_t* b) {
    asm volatile("mma.sync.aligned.m16n8k16.row.col.f32.f16.f16.f32 "
        "{%0,%1,%2,%3}, {%4,%5,%6,%7}, {%8,%9}, {%0,%1,%2,%3};"
        : "+f"(c[0]), "+f"(c[1]), "+f"(c[2]), "+f"(c[3])
        : "r"(a[0]), "r"(a[1]), "r"(a[2]), "r"(a[3]), "r"(b[0]), "r"(b[1]));
}

__device__ __forceinline__ uint32_t pack_h2(float lo, float hi) {
    __half2 h = __halves2half2(__float2half_rn(lo), __float2half_rn(hi));
    return *reinterpret_cast<uint32_t*>(&h);
}

// ---------------------------------------------------------------------------
// Warp-collective SDF eval for this warp's 32 points (one per lane).
// MMA roles: A = W2' (outputs m=128 x k=128, fp16 hi/lo from SMEM via ldmatrix),
// B = activations h (k=128 x n=8 points per tile), built DIRECTLY in registers:
// thread (q = lane&3, g = lane>>2) computes h[k = 2q,2q+1,2q+8,2q+9 (+16kt)]
// for point 8b+g.  3 products: Ah*Bh + Ah*Bl + Al*Bh, fp32 accumulate.
// ---------------------------------------------------------------------------
__device__ __noinline__ float sdf_eval_warp(float px, float py, float pz, float b3)
{
    extern __shared__ char dsm[];
    const int tid  = threadIdx.x;
    const int lane = tid & 31;
    const int q    = lane & 3;
    const int g    = lane >> 2;
    const int wbase = tid & ~31;
    const uint32_t smem0 = (uint32_t)__cvta_generic_to_shared(dsm);
    const float* sW1 = (const float*)(dsm + OFF_W1);
    const float* sb1 = (const float*)(dsm + OFF_B1);
    const float* sb2 = (const float*)(dsm + OFF_B2);
    const float* sW3 = (const float*)(dsm + OFF_W3);
    float* s_res = (float*)(dsm + OFF_RES);

    __syncwarp();   // prior eval's s_res reads complete before we overwrite

    const uint32_t lanebase =
        (uint32_t)((((lane >> 3) & 1) * 8 + (lane & 7)) * ROWB + (lane >> 4) * 16);

#pragma unroll 1
    for (int b = 0; b < 4; b++) {
        // coords of this thread's assigned point (8b + g) via warp shuffle
        int pb = 8 * b + g;
        float qx = __shfl_sync(0xFFFFFFFFu, px, pb);
        float qy = __shfl_sync(0xFFFFFFFFu, py, pb);
        float qz = __shfl_sync(0xFFFFFFFFu, pz, pb);

        // ---- layer 1 for exactly the h-values this thread's B fragment owns
        uint32_t bhi[8][2], blo[8][2];
#pragma unroll
        for (int kt = 0; kt < 8; kt++) {
            int k0 = kt * 16 + 2 * q;      // even -> float2 loads 8B aligned
            float2 w0a = *(const float2*)(sW1 + k0);
            float2 w0b = *(const float2*)(sW1 + k0 + 8);
            float2 w1a = *(const float2*)(sW1 + 128 + k0);
            float2 w1b = *(const float2*)(sW1 + 128 + k0 + 8);
            float2 w2a = *(const float2*)(sW1 + 256 + k0);
            float2 w2b = *(const float2*)(sW1 + 256 + k0 + 8);
            float2 b1a = *(const float2*)(sb1 + k0);
            float2 b1b = *(const float2*)(sb1 + k0 + 8);
            float h00 = fminf(softplusf(fmaf(qx, w0a.x, fmaf(qy, w1a.x, fmaf(qz, w2a.x, b1a.x)))), 60000.0f);
            float h01 = fminf(softplusf(fmaf(qx, w0a.y, fmaf(qy, w1a.y, fmaf(qz, w2a.y, b1a.y)))), 60000.0f);
            float h08 = fminf(softplusf(fmaf(qx, w0b.x, fmaf(qy, w1b.x, fmaf(qz, w2b.x, b1b.x)))), 60000.0f);
            float h09 = fminf(softplusf(fmaf(qx, w0b.y, fmaf(qy, w1b.y, fmaf(qz, w2b.y, b1b.y)))), 60000.0f);
            bhi[kt][0] = pack_h2(h00, h01);
            bhi[kt][1] = pack_h2(h08, h09);
            // lo residuals
            __half t0 = __float2half_rn(h00), t1 = __float2half_rn(h01);
            __half t8 = __float2half_rn(h08), t9 = __float2half_rn(h09);
            blo[kt][0] = pack_h2(h00 - __half2float(t0), h01 - __half2float(t1));
            blo[kt][1] = pack_h2(h08 - __half2float(t8), h09 - __half2float(t9));
        }

        // ---- GEMM over output tiles (m) + fused epilogue ----
        float p0 = 0.0f, p1 = 0.0f;    // partial dot(W3, softplus(d)) for pts 8b+2q, +1
#pragma unroll 1
        for (int mt = 0; mt < 8; mt++) {
            int o0 = mt * 16 + g, o1 = o0 + 8;
            float b2a = sb2[o0], b2b = sb2[o1];
            float cm[4] = {b2a, b2a, b2b, b2b};
            float cx[4] = {0.f, 0.f, 0.f, 0.f};
            uint32_t abase = smem0 + (uint32_t)(mt * 16 * ROWB) + lanebase;
#pragma unroll
            for (int kt = 0; kt < 8; kt++) {
                uint32_t ah[4], al[4];
                ldsm4(ah, abase + SW_HI + kt * 32);
                ldsm4(al, abase + SW_LO + kt * 32);
                mma16816(cm, ah, bhi[kt]);
                mma16816(cm, ah, blo[kt]);
                mma16816(cx, al, bhi[kt]);
            }
            float w3a = sW3[o0], w3b = sW3[o1];
            p0 = fmaf(softplusf(cm[0] + cx[0]), w3a,
                 fmaf(softplusf(cm[2] + cx[2]), w3b, p0));
            p1 = fmaf(softplusf(cm[1] + cx[1]), w3a,
                 fmaf(softplusf(cm[3] + cx[3]), w3b, p1));
        }
        // reduce across the 8 threads sharing each point column (vary g, fixed q)
        p0 += __shfl_xor_sync(0xFFFFFFFFu, p0, 4);
        p0 += __shfl_xor_sync(0xFFFFFFFFu, p0, 8);
        p0 += __shfl_xor_sync(0xFFFFFFFFu, p0, 16);
        p1 += __shfl_xor_sync(0xFFFFFFFFu, p1, 4);
        p1 += __shfl_xor_sync(0xFFFFFFFFu, p1, 8);
        p1 += __shfl_xor_sync(0xFFFFFFFFu, p1, 16);
        if (g == 0) {
            s_res[wbase + 8 * b + 2 * q + 0] = p0;
            s_res[wbase + 8 * b + 2 * q + 1] = p1;
        }
    }
    __syncwarp();
    return b3 + s_res[tid];
}

// ---------------------------------------------------------------------------
__global__ void __launch_bounds__(256, 2)
sphere_trace_kernel(const float* __restrict__ rays_d,
                    const float* __restrict__ rays_o,
                    const float* __restrict__ gW1,
                    const float* __restrict__ gb1,
                    const float* __restrict__ gW2,
                    const float* __restrict__ gb2,
                    const float* __restrict__ gW3,
                    const float* __restrict__ gb3,
                    float* __restrict__ out,
                    int n)
{
    extern __shared__ char dsm[];
    const int tid = threadIdx.x;

    // stage W2' hi/lo fp16: W2'[m][k] = W2[k][m] = gW2[k*128+m]; reads coalesced
    for (int idx = tid; idx < HID * HID; idx += blockDim.x) {
        int m = idx & 127, k = idx >> 7;
        float w = gW2[idx];
        __half h = __float2half_rn(w);
        __half l = __float2half_rn(w - __half2float(h));
        *(__half*)(dsm + SW_HI + m * ROWB + k * 2) = h;
        *(__half*)(dsm + SW_LO + m * ROWB + k * 2) = l;
    }
    {
        float* sW1 = (float*)(dsm + OFF_W1);
        float* sb1 = (float*)(dsm + OFF_B1);
        float* sb2 = (float*)(dsm + OFF_B2);
        float* sW3 = (float*)(dsm + OFF_W3);
        for (int i = tid; i < 3 * HID; i += blockDim.x) sW1[i] = gW1[i];
        for (int i = tid; i < HID; i += blockDim.x) {
            sb1[i] = gb1[i];
            sb2[i] = gb2[i];
            sW3[i] = gW3[i];
        }
    }
    float b3 = gb3[0];
    __syncthreads();

    const int total = 2 * n;
    int t = blockIdx.x * blockDim.x + tid;
    const bool valid = (t < total);
    int tc  = valid ? t : (total - 1);
    int ray = tc >> 1;
    int ch  = tc & 1;
    float sgn = ch ? -1.0f : 1.0f;

    float dx = rays_d[ray * 3 + 0];
    float dy = rays_d[ray * 3 + 1];
    float dz = rays_d[ray * 3 + 2];
    float ox = rays_o[ray * 3 + 0];
    float oy = rays_o[ray * 3 + 1];
    float oz = rays_o[ray * 3 + 2];

    float z = 0.0f;
    float next_sdf = sdf_eval_warp(ox, oy, oz, b3);
    bool mask = true;

#pragma unroll 1
    for (int it = 0; it < 6; it++) {
        float sdf_vals = mask ? next_sdf : 0.0f;
        if (sdf_vals <= SDF_THRESH) sdf_vals = 0.0f;
        mask = mask && (sdf_vals > SDF_THRESH);
        z = fmaf(sgn, sdf_vals, z);

        if (__any_sync(0xFFFFFFFFu, mask)) {
            float s = sdf_eval_warp(fmaf(z, dx, ox), fmaf(z, dy, oy),
                                    fmaf(z, dz, oz), b3);
            next_sdf = mask ? s : 0.0f;
        } else {
            next_sdf = 0.0f;
        }

        bool fmask = next_sdf < 0.0f;
#pragma unroll 1
        for (int i = 0; i < 3; i++) {
            float step = 0.5f / (float)(1 << i);   // 0.5, 0.25, 0.125 exact
            if (__any_sync(0xFFFFFFFFu, fmask)) {
                float zc = fmask ? (z - step * sgn * sdf_vals) : z;
                float s2 = sdf_eval_warp(fmaf(zc, dx, ox), fmaf(zc, dy, oy),
                                         fmaf(zc, dz, oz), b3);
                z = zc;
                if (fmask) next_sdf = s2;
            }
            fmask = next_sdf < 0.0f;
        }

        // mask &= (z_ch0 < z_ch1): channels are adjacent lanes
        float zo = __shfl_xor_sync(0xFFFFFFFFu, z, 1);
        bool cond = (ch == 0) ? (z < zo) : (zo < z);
        mask = mask && cond;
    }

    {   // final top-of-loop mask update
        float sdf_vals = mask ? next_sdf : 0.0f;
        if (sdf_vals <= SDF_THRESH) sdf_vals = 0.0f;
        mask = mask && (sdf_vals > SDF_THRESH);
    }

    if (valid) {
        float px = fmaf(z, dx, ox);
        float py = fmaf(z, dy, oy);
        float pz = fmaf(z, dz, oz);
        long basei = (long)ch * n + ray;
        // output layout: points (2,n,3) | z_vals (2,n) | mask (2,n)
        out[basei * 3 + 0] = px;
        out[basei * 3 + 1] = py;
        out[basei * 3 + 2] = pz;
        out[(long)6 * n + basei] = z;
        out[(long)8 * n + basei] = mask ? 1.0f : 0.0f;
    }
}

extern "C" void kernel_launch(void* const* d_in, const int* in_sizes, int n_in,
                              void* d_out, int out_size)
{
    const float* rays_d = (const float*)d_in[0];
    const float* rays_o = (const float*)d_in[1];
    const float* W1     = (const float*)d_in[2];
    const float* b1     = (const float*)d_in[3];
    const float* W2     = (const float*)d_in[4];
    const float* b2     = (const float*)d_in[5];
    const float* W3     = (const float*)d_in[6];
    const float* b3     = (const float*)d_in[7];

    int n = in_sizes[0] / 3;        // N_RAYS
    int total = 2 * n;
    int block = 256;
    int grid = (total + block - 1) / block;

    cudaFuncSetAttribute(sphere_trace_kernel,
                         cudaFuncAttributeMaxDynamicSharedMemorySize,
                         SMEM_TOTAL);

    sphere_trace_kernel<<<grid, block, SMEM_TOTAL>>>(
        rays_d, rays_o, W1, b1, W2, b2, W3, b3, (float*)d_out, n);
}

// round 6
// speedup vs baseline: 4.7206x; 1.4163x over previous
#include <cuda_runtime.h>
#include <cuda_fp16.h>
#include <cstdint>
#include <math.h>

#define HID 128
#define SDF_THRESH 5e-05f
#define ROWB 272              // padded row stride (bytes) for fp16[128] rows

// shared-memory byte offsets (per-CTA dynamic, all 16B aligned)
#define SW_HI  0              // W2' hi: 128 rows x 272B = 34816  (W2'[m][k] = W2[k][m])
#define SW_LO  34816          // W2' lo: 34816
#define OFF_W1 69632          // fp32 [3][128] = 1536
#define OFF_B1 71168          // 512
#define OFF_B2 71680          // 512
#define OFF_W3 72192          // 512
#define OFF_RES 72704         // fp32 [256] = 1024
#define SMEM_TOTAL 73728      // 72 KB -> 2 CTAs/SM

// softplus: max(x,0) + log(1 + exp(-|x|))
__device__ __forceinline__ float softplusf(float x) {
    float u = __expf(-fabsf(x));
    return fmaxf(x, 0.0f) + __logf(1.0f + u);
}

__device__ __forceinline__ void ldsm4(uint32_t* r, uint32_t a) {
    asm volatile("ldmatrix.sync.aligned.m8n8.x4.shared.b16 {%0,%1,%2,%3}, [%4];"
        : "=r"(r[0]), "=r"(r[1]), "=r"(r[2]), "=r"(r[3]) : "r"(a));
}
__device__ __forceinline__ void mma16816(float* c, const uint32_t* a, const uint32_t* b) {
    asm volatile("mma.sync.aligned.m16n8k16.row.col.f32.f16.f16.f32 "
        "{%0,%1,%2,%3}, {%4,%5,%6,%7}, {%8,%9}, {%0,%1,%2,%3};"
        : "+f"(c[0]), "+f"(c[1]), "+f"(c[2]), "+f"(c[3])
        : "r"(a[0]), "r"(a[1]), "r"(a[2]), "r"(a[3]), "r"(b[0]), "r"(b[1]));
}

__device__ __forceinline__ uint32_t pack_h2(float lo, float hi) {
    __half2 h = __halves2half2(__float2half_rn(lo), __float2half_rn(hi));
    return *reinterpret_cast<uint32_t*>(&h);
}

// layer-1 B fragments for one 8-point group: thread (q) computes
// h[k = 16kt + 2q, 2q+1, 2q+8, 2q+9] for its point, hi + lo fp16 split.
__device__ __forceinline__ void layer1_frags(
    float qx, float qy, float qz, int q,
    const float* __restrict__ sW1, const float* __restrict__ sb1,
    uint32_t (&bhi)[8][2], uint32_t (&blo)[8][2])
{
#pragma unroll
    for (int kt = 0; kt < 8; kt++) {
        int k0 = kt * 16 + 2 * q;
        float2 w0a = *(const float2*)(sW1 + k0);
        float2 w0b = *(const float2*)(sW1 + k0 + 8);
        float2 w1a = *(const float2*)(sW1 + 128 + k0);
        float2 w1b = *(const float2*)(sW1 + 128 + k0 + 8);
        float2 w2a = *(const float2*)(sW1 + 256 + k0);
        float2 w2b = *(const float2*)(sW1 + 256 + k0 + 8);
        float2 b1a = *(const float2*)(sb1 + k0);
        float2 b1b = *(const float2*)(sb1 + k0 + 8);
        float h00 = fminf(softplusf(fmaf(qx, w0a.x, fmaf(qy, w1a.x, fmaf(qz, w2a.x, b1a.x)))), 60000.0f);
        float h01 = fminf(softplusf(fmaf(qx, w0a.y, fmaf(qy, w1a.y, fmaf(qz, w2a.y, b1a.y)))), 60000.0f);
        float h08 = fminf(softplusf(fmaf(qx, w0b.x, fmaf(qy, w1b.x, fmaf(qz, w2b.x, b1b.x)))), 60000.0f);
        float h09 = fminf(softplusf(fmaf(qx, w0b.y, fmaf(qy, w1b.y, fmaf(qz, w2b.y, b1b.y)))), 60000.0f);
        bhi[kt][0] = pack_h2(h00, h01);
        bhi[kt][1] = pack_h2(h08, h09);
        __half t0 = __float2half_rn(h00), t1 = __float2half_rn(h01);
        __half t8 = __float2half_rn(h08), t9 = __float2half_rn(h09);
        blo[kt][0] = pack_h2(h00 - __half2float(t0), h01 - __half2float(t1));
        blo[kt][1] = pack_h2(h08 - __half2float(t8), h09 - __half2float(t9));
    }
}

// ---------------------------------------------------------------------------
// Warp-collective SDF eval with 8-point-group gating.
// A = W2' fp16 hi/lo from SMEM (ldmatrix); B = activations built in regs.
// Paired path: two groups share every A-fragment load (6 mma per ldsm pair).
// ---------------------------------------------------------------------------
__device__ __noinline__ float sdf_eval_warp(float px, float py, float pz,
                                            bool need, float b3)
{
    extern __shared__ char dsm[];
    const int tid  = threadIdx.x;
    const int lane = tid & 31;
    const int q    = lane & 3;
    const int g    = lane >> 2;
    const int wbase = tid & ~31;
    const uint32_t smem0 = (uint32_t)__cvta_generic_to_shared(dsm);
    const float* sW1 = (const float*)(dsm + OFF_W1);
    const float* sb1 = (const float*)(dsm + OFF_B1);
    const float* sb2 = (const float*)(dsm + OFF_B2);
    const float* sW3 = (const float*)(dsm + OFF_W3);
    float* s_res = (float*)(dsm + OFF_RES);

    __syncwarp();   // prior eval's s_res reads complete before we overwrite

    const uint32_t lanebase =
        (uint32_t)((((lane >> 3) & 1) * 8 + (lane & 7)) * ROWB + (lane >> 4) * 16);
    const uint32_t bal = __ballot_sync(0xFFFFFFFFu, need);

#pragma unroll 1
    for (int p = 0; p < 2; p++) {
        const int b0 = 2 * p, b1 = 2 * p + 1;
        const bool a0 = ((bal >> (8 * b0)) & 0xFFu) != 0;
        const bool a1 = ((bal >> (8 * b1)) & 0xFFu) != 0;
        if (!(a0 || a1)) continue;

        if (a0 && a1) {
            // ---------------- paired path: both groups share A loads -------
            int pb0 = 8 * b0 + g, pb1 = pb0 + 8;
            float q0x = __shfl_sync(0xFFFFFFFFu, px, pb0);
            float q0y = __shfl_sync(0xFFFFFFFFu, py, pb0);
            float q0z = __shfl_sync(0xFFFFFFFFu, pz, pb0);
            float q1x = __shfl_sync(0xFFFFFFFFu, px, pb1);
            float q1y = __shfl_sync(0xFFFFFFFFu, py, pb1);
            float q1z = __shfl_sync(0xFFFFFFFFu, pz, pb1);
            uint32_t h0[8][2], l0[8][2], h1[8][2], l1[8][2];
            layer1_frags(q0x, q0y, q0z, q, sW1, sb1, h0, l0);
            layer1_frags(q1x, q1y, q1z, q, sW1, sb1, h1, l1);

            float P0 = 0.f, P1 = 0.f, P2 = 0.f, P3 = 0.f;
#pragma unroll 1
            for (int mt = 0; mt < 8; mt++) {
                int o0 = mt * 16 + g, o1 = o0 + 8;
                float b2a = sb2[o0], b2b = sb2[o1];
                float c0[4] = {b2a, b2a, b2b, b2b};
                float c1[4] = {b2a, b2a, b2b, b2b};
                uint32_t abase = smem0 + (uint32_t)(mt * 16 * ROWB) + lanebase;
#pragma unroll
                for (int kt = 0; kt < 8; kt++) {
                    uint32_t ah[4], al[4];
                    ldsm4(ah, abase + SW_HI + kt * 32);
                    ldsm4(al, abase + SW_LO + kt * 32);
                    mma16816(c0, ah, h0[kt]);
                    mma16816(c0, ah, l0[kt]);
                    mma16816(c0, al, h0[kt]);
                    mma16816(c1, ah, h1[kt]);
                    mma16816(c1, ah, l1[kt]);
                    mma16816(c1, al, h1[kt]);
                }
                float w3a = sW3[o0], w3b = sW3[o1];
                P0 = fmaf(softplusf(c0[0]), w3a, fmaf(softplusf(c0[2]), w3b, P0));
                P1 = fmaf(softplusf(c0[1]), w3a, fmaf(softplusf(c0[3]), w3b, P1));
                P2 = fmaf(softplusf(c1[0]), w3a, fmaf(softplusf(c1[2]), w3b, P2));
                P3 = fmaf(softplusf(c1[1]), w3a, fmaf(softplusf(c1[3]), w3b, P3));
            }
            P0 += __shfl_xor_sync(0xFFFFFFFFu, P0, 4);
            P0 += __shfl_xor_sync(0xFFFFFFFFu, P0, 8);
            P0 += __shfl_xor_sync(0xFFFFFFFFu, P0, 16);
            P1 += __shfl_xor_sync(0xFFFFFFFFu, P1, 4);
            P1 += __shfl_xor_sync(0xFFFFFFFFu, P1, 8);
            P1 += __shfl_xor_sync(0xFFFFFFFFu, P1, 16);
            P2 += __shfl_xor_sync(0xFFFFFFFFu, P2, 4);
            P2 += __shfl_xor_sync(0xFFFFFFFFu, P2, 8);
            P2 += __shfl_xor_sync(0xFFFFFFFFu, P2, 16);
            P3 += __shfl_xor_sync(0xFFFFFFFFu, P3, 4);
            P3 += __shfl_xor_sync(0xFFFFFFFFu, P3, 8);
            P3 += __shfl_xor_sync(0xFFFFFFFFu, P3, 16);
            if (g == 0) {
                s_res[wbase + 8 * b0 + 2 * q + 0] = P0;
                s_res[wbase + 8 * b0 + 2 * q + 1] = P1;
                s_res[wbase + 8 * b1 + 2 * q + 0] = P2;
                s_res[wbase + 8 * b1 + 2 * q + 1] = P3;
            }
        } else {
            // ---------------- single-group path ----------------------------
            int b = a0 ? b0 : b1;
            int pb = 8 * b + g;
            float qx = __shfl_sync(0xFFFFFFFFu, px, pb);
            float qy = __shfl_sync(0xFFFFFFFFu, py, pb);
            float qz = __shfl_sync(0xFFFFFFFFu, pz, pb);
            uint32_t bh[8][2], bl[8][2];
            layer1_frags(qx, qy, qz, q, sW1, sb1, bh, bl);

            float P0 = 0.f, P1 = 0.f;
#pragma unroll 1
            for (int mt = 0; mt < 8; mt++) {
                int o0 = mt * 16 + g, o1 = o0 + 8;
                float b2a = sb2[o0], b2b = sb2[o1];
                float c[4] = {b2a, b2a, b2b, b2b};
                uint32_t abase = smem0 + (uint32_t)(mt * 16 * ROWB) + lanebase;
#pragma unroll
                for (int kt = 0; kt < 8; kt++) {
                    uint32_t ah[4], al[4];
                    ldsm4(ah, abase + SW_HI + kt * 32);
                    ldsm4(al, abase + SW_LO + kt * 32);
                    mma16816(c, ah, bh[kt]);
                    mma16816(c, ah, bl[kt]);
                    mma16816(c, al, bh[kt]);
                }
                float w3a = sW3[o0], w3b = sW3[o1];
                P0 = fmaf(softplusf(c[0]), w3a, fmaf(softplusf(c[2]), w3b, P0));
                P1 = fmaf(softplusf(c[1]), w3a, fmaf(softplusf(c[3]), w3b, P1));
            }
            P0 += __shfl_xor_sync(0xFFFFFFFFu, P0, 4);
            P0 += __shfl_xor_sync(0xFFFFFFFFu, P0, 8);
            P0 += __shfl_xor_sync(0xFFFFFFFFu, P0, 16);
            P1 += __shfl_xor_sync(0xFFFFFFFFu, P1, 4);
            P1 += __shfl_xor_sync(0xFFFFFFFFu, P1, 8);
            P1 += __shfl_xor_sync(0xFFFFFFFFu, P1, 16);
            if (g == 0) {
                s_res[wbase + 8 * b + 2 * q + 0] = P0;
                s_res[wbase + 8 * b + 2 * q + 1] = P1;
            }
        }
    }
    __syncwarp();
    return b3 + s_res[tid];
}

// ---------------------------------------------------------------------------
__global__ void __launch_bounds__(256, 2)
sphere_trace_kernel(const float* __restrict__ rays_d,
                    const float* __restrict__ rays_o,
                    const float* __restrict__ gW1,
                    const float* __restrict__ gb1,
                    const float* __restrict__ gW2,
                    const float* __restrict__ gb2,
                    const float* __restrict__ gW3,
                    const float* __restrict__ gb3,
                    float* __restrict__ out,
                    int n)
{
    extern __shared__ char dsm[];
    const int tid = threadIdx.x;

    // stage W2' hi/lo fp16: W2'[m][k] = W2[k][m] = gW2[k*128+m]; reads coalesced
    for (int idx = tid; idx < HID * HID; idx += blockDim.x) {
        int m = idx & 127, k = idx >> 7;
        float w = gW2[idx];
        __half h = __float2half_rn(w);
        __half l = __float2half_rn(w - __half2float(h));
        *(__half*)(dsm + SW_HI + m * ROWB + k * 2) = h;
        *(__half*)(dsm + SW_LO + m * ROWB + k * 2) = l;
    }
    {
        float* sW1 = (float*)(dsm + OFF_W1);
        float* sb1 = (float*)(dsm + OFF_B1);
        float* sb2 = (float*)(dsm + OFF_B2);
        float* sW3 = (float*)(dsm + OFF_W3);
        for (int i = tid; i < 3 * HID; i += blockDim.x) sW1[i] = gW1[i];
        for (int i = tid; i < HID; i += blockDim.x) {
            sb1[i] = gb1[i];
            sb2[i] = gb2[i];
            sW3[i] = gW3[i];
        }
    }
    float b3 = gb3[0];
    __syncthreads();

    const int total = 2 * n;
    int t = blockIdx.x * blockDim.x + tid;
    const bool valid = (t < total);
    int tc  = valid ? t : (total - 1);
    int ray = tc >> 1;
    int ch  = tc & 1;
    float sgn = ch ? -1.0f : 1.0f;

    float dx = rays_d[ray * 3 + 0];
    float dy = rays_d[ray * 3 + 1];
    float dz = rays_d[ray * 3 + 2];
    float ox = rays_o[ray * 3 + 0];
    float oy = rays_o[ray * 3 + 1];
    float oz = rays_o[ray * 3 + 2];

    float z = 0.0f;
    float next_sdf = sdf_eval_warp(ox, oy, oz, true, b3);
    bool mask = true;

#pragma unroll 1
    for (int it = 0; it < 6; it++) {
        float sdf_vals = mask ? next_sdf : 0.0f;
        if (sdf_vals <= SDF_THRESH) sdf_vals = 0.0f;
        mask = mask && (sdf_vals > SDF_THRESH);
        z = fmaf(sgn, sdf_vals, z);

        if (__any_sync(0xFFFFFFFFu, mask)) {
            float s = sdf_eval_warp(fmaf(z, dx, ox), fmaf(z, dy, oy),
                                    fmaf(z, dz, oz), mask, b3);
            next_sdf = mask ? s : 0.0f;
        } else {
            next_sdf = 0.0f;
        }

        bool fmask = next_sdf < 0.0f;
#pragma unroll 1
        for (int i = 0; i < 3; i++) {
            float step = 0.5f / (float)(1 << i);   // 0.5, 0.25, 0.125 exact
            if (__any_sync(0xFFFFFFFFu, fmask)) {
                float zc = fmask ? (z - step * sgn * sdf_vals) : z;
                float s2 = sdf_eval_warp(fmaf(zc, dx, ox), fmaf(zc, dy, oy),
                                         fmaf(zc, dz, oz), fmask, b3);
                z = zc;
                if (fmask) next_sdf = s2;
            }
            fmask = next_sdf < 0.0f;
        }

        // mask &= (z_ch0 < z_ch1): channels are adjacent lanes
        float zo = __shfl_xor_sync(0xFFFFFFFFu, z, 1);
        bool cond = (ch == 0) ? (z < zo) : (zo < z);
        mask = mask && cond;
    }

    {   // final top-of-loop mask update
        float sdf_vals = mask ? next_sdf : 0.0f;
        if (sdf_vals <= SDF_THRESH) sdf_vals = 0.0f;
        mask = mask && (sdf_vals > SDF_THRESH);
    }

    if (valid) {
        float px = fmaf(z, dx, ox);
        float py = fmaf(z, dy, oy);
        float pz = fmaf(z, dz, oz);
        long basei = (long)ch * n + ray;
        // output layout: points (2,n,3) | z_vals (2,n) | mask (2,n)
        out[basei * 3 + 0] = px;
        out[basei * 3 + 1] = py;
        out[basei * 3 + 2] = pz;
        out[(long)6 * n + basei] = z;
        out[(long)8 * n + basei] = mask ? 1.0f : 0.0f;
    }
}

extern "C" void kernel_launch(void* const* d_in, const int* in_sizes, int n_in,
                              void* d_out, int out_size)
{
    const float* rays_d = (const float*)d_in[0];
    const float* rays_o = (const float*)d_in[1];
    const float* W1     = (const float*)d_in[2];
    const float* b1     = (const float*)d_in[3];
    const float* W2     = (const float*)d_in[4];
    const float* b2     = (const float*)d_in[5];
    const float* W3     = (const float*)d_in[6];
    const float* b3     = (const float*)d_in[7];

    int n = in_sizes[0] / 3;        // N_RAYS
    int total = 2 * n;
    int block = 256;
    int grid = (total + block - 1) / block;

    cudaFuncSetAttribute(sphere_trace_kernel,
                         cudaFuncAttributeMaxDynamicSharedMemorySize,
                         SMEM_TOTAL);

    sphere_trace_kernel<<<grid, block, SMEM_TOTAL>>>(
        rays_d, rays_o, W1, b1, W2, b2, W3, b3, (float*)d_out, n);
}